// round 1
// baseline (speedup 1.0000x reference)
#include <cuda_runtime.h>
#include <cstdio>

#define BB 4
#define LL 1024
#define DIN 8
#define DMODEL 512
#define NDEPTH 4
#define DINNER 1024
#define DSTATE 16
#define DCONV 4
#define DTRANK 32
#define MROWS (BB*LL)   /* 4096 */

// ---------------- scratch (no allocations allowed) ----------------
__device__ float g_h[MROWS*DMODEL];        // hidden (4096x512)
__device__ float g_xz[MROWS*2*DINNER];     // xz (4096x2048): [:,:1024]=xc, [:,1024:]=z
__device__ float g_u[MROWS*DINNER];        // silu(conv(xc))
__device__ float g_sz[MROWS*DINNER];       // silu(z)
__device__ float g_xdbl[MROWS*64];         // [dt_lr(32) | B(16) | C(16)]
__device__ float g_dt[MROWS*DINNER];       // softplus dt
__device__ float g_y[MROWS*DINNER];        // scan output (ready for out-GEMM)

// ---------------- fast math helpers ----------------
__device__ __forceinline__ float fx2(float x){ float y; asm("ex2.approx.f32 %0,%1;" : "=f"(y) : "f"(x)); return y; }
__device__ __forceinline__ float fexp(float x){ return fx2(x*1.4426950408889634f); }
__device__ __forceinline__ float fsilu(float x){ return x/(1.f+fexp(-x)); }

// ---------------- input projection: h = x @ in_w^T + in_b ----------------
__global__ void inproj_kernel(const float* __restrict__ x, const float* __restrict__ w,
                              const float* __restrict__ b){
    int idx = blockIdx.x*blockDim.x + threadIdx.x;
    if (idx >= MROWS*DMODEL) return;
    int m = idx / DMODEL, d = idx % DMODEL;
    const float* xr = x + m*DIN;
    const float* wr = w + d*DIN;
    float acc = b[d];
#pragma unroll
    for (int i = 0; i < DIN; i++) acc += xr[i]*wr[i];
    g_h[idx] = acc;
}

// ---------------- generic fp32 NT GEMM: C[m,n] = sum_k A[m,k]*B[n,k] ----------------
// BM=128, BN=64, BK=16, 256 threads, 8x4 microtile.
// EPI: 0 = none, 1 = softplus(c + bias[n])
template<int EPI>
__global__ __launch_bounds__(256)
void gemm_nt(const float* __restrict__ A, const float* __restrict__ B, float* __restrict__ C,
             int K, int lda, int ldb, int ldc, const float* __restrict__ bias){
    __shared__ float As[16][132];
    __shared__ float Bs[16][68];
    const int tid = threadIdx.x;
    const int tx = tid & 15;          // 0..15 -> N
    const int ty = tid >> 4;          // 0..15 -> M
    const int bx = blockIdx.x, by = blockIdx.y;

    float acc[8][4];
#pragma unroll
    for (int i = 0; i < 8; i++)
#pragma unroll
        for (int j = 0; j < 4; j++) acc[i][j] = 0.f;

    const float* Ab = A + (size_t)by*128*lda;
    const float* Bb = B + (size_t)bx*64*ldb;

    for (int kt = 0; kt < K; kt += 16){
        // A tile: 128 rows x 16 k = 512 float4, 2 per thread
#pragma unroll
        for (int it = 0; it < 2; it++){
            int i = tid*2 + it;
            int r = i >> 2, c4 = i & 3;
            float4 v = *reinterpret_cast<const float4*>(Ab + (size_t)r*lda + kt + c4*4);
            As[c4*4+0][r] = v.x; As[c4*4+1][r] = v.y;
            As[c4*4+2][r] = v.z; As[c4*4+3][r] = v.w;
        }
        // B tile: 64 rows x 16 k = 256 float4, 1 per thread
        {
            int r = tid >> 2, c4 = tid & 3;
            float4 v = *reinterpret_cast<const float4*>(Bb + (size_t)r*ldb + kt + c4*4);
            Bs[c4*4+0][r] = v.x; Bs[c4*4+1][r] = v.y;
            Bs[c4*4+2][r] = v.z; Bs[c4*4+3][r] = v.w;
        }
        __syncthreads();
#pragma unroll
        for (int kk = 0; kk < 16; kk++){
            float a[8], bv[4];
#pragma unroll
            for (int i = 0; i < 8; i++) a[i] = As[kk][ty*8+i];
#pragma unroll
            for (int j = 0; j < 4; j++) bv[j] = Bs[kk][tx*4+j];
#pragma unroll
            for (int i = 0; i < 8; i++)
#pragma unroll
                for (int j = 0; j < 4; j++) acc[i][j] += a[i]*bv[j];
        }
        __syncthreads();
    }

#pragma unroll
    for (int i = 0; i < 8; i++){
        int row = by*128 + ty*8 + i;
#pragma unroll
        for (int j = 0; j < 4; j++){
            int col = bx*64 + tx*4 + j;
            float v = acc[i][j];
            if (EPI == 1){
                v += bias[col];
                v = (v > 20.f) ? v : log1pf(fexp(v));   // softplus
            }
            C[(size_t)row*ldc + col] = v;
        }
    }
}

// ---------------- causal conv1d + silu, plus silu(z) ----------------
__global__ void conv_silu_kernel(const float* __restrict__ cw, const float* __restrict__ cb){
    int idx = blockIdx.x*blockDim.x + threadIdx.x;
    if (idx >= MROWS*DINNER) return;
    int r = idx / DINNER, e = idx % DINNER;
    int b = r / LL, l = r % LL;
    float acc = cb[e];
#pragma unroll
    for (int k = 0; k < DCONV; k++){
        int lp = l - (DCONV-1) + k;
        if (lp >= 0)
            acc += cw[e*DCONV + k] * g_xz[((size_t)(b*LL + lp))*(2*DINNER) + e];
    }
    g_u[idx] = fsilu(acc);
    float z = g_xz[(size_t)r*(2*DINNER) + DINNER + e];
    g_sz[idx] = fsilu(z);
}

// ---------------- selective scan (sequential in t, parallel over b,d) ----------------
// grid: (DINNER/128, BB), block 128. One channel per thread, 16 states in regs.
// Fuses: y = (scan_y + u*Dp) * silu(z)
__global__ __launch_bounds__(128)
void scan_kernel(const float* __restrict__ A_log, const float* __restrict__ Dp){
    const int b = blockIdx.y;
    const int d = blockIdx.x*128 + threadIdx.x;

    float a2[DSTATE];
#pragma unroll
    for (int s = 0; s < DSTATE; s++)
        a2[s] = -expf(A_log[d*DSTATE + s]) * 1.4426950408889634f;  // so dA = ex2(dt*a2)
    const float dp = Dp[d];

    float st[DSTATE];
#pragma unroll
    for (int s = 0; s < DSTATE; s++) st[s] = 0.f;

    __shared__ float sBC[64][32];   // 64 timesteps of [B(16) | C(16)]

    for (int t0 = 0; t0 < LL; t0 += 64){
        for (int i = threadIdx.x; i < 64*32; i += 128){
            int tt = i >> 5, j = i & 31;
            sBC[tt][j] = g_xdbl[((size_t)(b*LL + t0 + tt))*64 + DTRANK + j];
        }
        __syncthreads();
#pragma unroll 4
        for (int tt = 0; tt < 64; tt++){
            size_t idx = ((size_t)(b*LL + t0 + tt))*DINNER + d;
            float dt = g_dt[idx];
            float uu = g_u[idx];
            float du = dt*uu;
            float y = 0.f;
#pragma unroll
            for (int s = 0; s < DSTATE; s++){
                float dA = fx2(dt*a2[s]);
                st[s] = dA*st[s] + sBC[tt][s]*du;
                y += st[s]*sBC[tt][16+s];
            }
            y = (y + uu*dp) * g_sz[idx];
            g_y[idx] = y;
        }
        __syncthreads();
    }
}

// ---------------- final layernorm ----------------
__global__ __launch_bounds__(128)
void ln_kernel(const float* __restrict__ gamma, const float* __restrict__ beta,
               float* __restrict__ out){
    const int m = blockIdx.x;
    const int tid = threadIdx.x;
    const float4 v = reinterpret_cast<const float4*>(g_h + (size_t)m*DMODEL)[tid];
    float s  = v.x + v.y + v.z + v.w;
    float sq = v.x*v.x + v.y*v.y + v.z*v.z + v.w*v.w;
#pragma unroll
    for (int off = 16; off; off >>= 1){
        s  += __shfl_xor_sync(0xffffffffu, s,  off);
        sq += __shfl_xor_sync(0xffffffffu, sq, off);
    }
    __shared__ float r1[4], r2[4];
    if ((tid & 31) == 0){ r1[tid>>5] = s; r2[tid>>5] = sq; }
    __syncthreads();
    s  = r1[0] + r1[1] + r1[2] + r1[3];
    sq = r2[0] + r2[1] + r2[2] + r2[3];
    float mu  = s * (1.f/DMODEL);
    float var = sq * (1.f/DMODEL) - mu*mu;
    float rs  = rsqrtf(var + 1e-5f);
    float4 g4 = reinterpret_cast<const float4*>(gamma)[tid];
    float4 b4 = reinterpret_cast<const float4*>(beta)[tid];
    float4 o;
    o.x = (v.x - mu)*rs*g4.x + b4.x;
    o.y = (v.y - mu)*rs*g4.y + b4.y;
    o.z = (v.z - mu)*rs*g4.z + b4.z;
    o.w = (v.w - mu)*rs*g4.w + b4.w;
    reinterpret_cast<float4*>(out + (size_t)m*DMODEL)[tid] = o;
}

// ---------------- launch ----------------
extern "C" void kernel_launch(void* const* d_in, const int* in_sizes, int n_in,
                              void* d_out, int out_size){
    const float* x       = (const float*)d_in[0];
    const float* in_w    = (const float*)d_in[1];
    const float* in_b    = (const float*)d_in[2];
    const float* W_xz    = (const float*)d_in[3];
    const float* conv_w  = (const float*)d_in[4];
    const float* conv_b  = (const float*)d_in[5];
    const float* W_xp    = (const float*)d_in[6];
    const float* W_dt    = (const float*)d_in[7];
    const float* b_dt    = (const float*)d_in[8];
    const float* A_log   = (const float*)d_in[9];
    const float* D_param = (const float*)d_in[10];
    const float* W_out   = (const float*)d_in[11];
    const float* ln_g    = (const float*)d_in[12];
    const float* ln_b    = (const float*)d_in[13];
    float* out = (float*)d_out;

    float *ph, *pxz, *pu, *pxdbl, *pdt, *py;
    cudaGetSymbolAddress((void**)&ph,    g_h);
    cudaGetSymbolAddress((void**)&pxz,   g_xz);
    cudaGetSymbolAddress((void**)&pu,    g_u);
    cudaGetSymbolAddress((void**)&pxdbl, g_xdbl);
    cudaGetSymbolAddress((void**)&pdt,   g_dt);
    cudaGetSymbolAddress((void**)&py,    g_y);

    inproj_kernel<<<(MROWS*DMODEL)/128, 128>>>(x, in_w, in_b);

    for (int lyr = 0; lyr < NDEPTH; lyr++){
        // xz = h @ Wxz^T           M=4096 N=2048 K=512
        gemm_nt<0><<<dim3(2048/64, MROWS/128), 256>>>(
            ph, W_xz + (size_t)lyr*2048*DMODEL, pxz,
            DMODEL, DMODEL, DMODEL, 2*DINNER, nullptr);

        conv_silu_kernel<<<(MROWS*DINNER)/256, 256>>>(
            conv_w + (size_t)lyr*DINNER*DCONV, conv_b + (size_t)lyr*DINNER);

        // xdbl = u @ Wxp^T         M=4096 N=64 K=1024
        gemm_nt<0><<<dim3(64/64, MROWS/128), 256>>>(
            pu, W_xp + (size_t)lyr*64*DINNER, pxdbl,
            DINNER, DINNER, DINNER, 64, nullptr);

        // dt = softplus(dt_lr @ Wdt^T + b_dt)   M=4096 N=1024 K=32 (lda=64)
        gemm_nt<1><<<dim3(DINNER/64, MROWS/128), 256>>>(
            pxdbl, W_dt + (size_t)lyr*DINNER*DTRANK, pdt,
            DTRANK, 64, DTRANK, DINNER, b_dt + (size_t)lyr*DINNER);

        scan_kernel<<<dim3(DINNER/128, BB), 128>>>(
            A_log + (size_t)lyr*DINNER*DSTATE, D_param + (size_t)lyr*DINNER);

        // h = y @ Wout^T           M=4096 N=512 K=1024
        gemm_nt<0><<<dim3(DMODEL/64, MROWS/128), 256>>>(
            py, W_out + (size_t)lyr*DMODEL*DINNER, ph,
            DINNER, DINNER, DINNER, DMODEL, nullptr);
    }

    ln_kernel<<<MROWS, 128>>>(ln_g, ln_b, out);
}

// round 3
// speedup vs baseline: 1.1733x; 1.1733x over previous
#include <cuda_runtime.h>
#include <cstdio>
#include <cstdint>

#define BB 4
#define LL 1024
#define DIN 8
#define DMODEL 512
#define NDEPTH 4
#define DINNER 1024
#define DSTATE 16
#define DCONV 4
#define DTRANK 32
#define MROWS (BB*LL)   /* 4096 */

// ---------------- scratch (no allocations allowed) ----------------
__device__ float g_h[MROWS*DMODEL];        // hidden (4096x512)
__device__ float g_xz[MROWS*2*DINNER];     // xz (4096x2048): [:,:1024]=xc, [:,1024:]=z
__device__ float g_u[MROWS*DINNER];        // silu(conv(xc))
__device__ float g_sz[MROWS*DINNER];       // silu(z)
__device__ float g_xdbl[MROWS*64];         // [dt_lr(32) | B(16) | C(16)]
__device__ float g_dt[MROWS*DINNER];       // softplus dt
__device__ float g_y[MROWS*DINNER];        // scan output

// ---------------- fast math helpers ----------------
__device__ __forceinline__ float fx2(float x){ float y; asm("ex2.approx.f32 %0,%1;" : "=f"(y) : "f"(x)); return y; }
__device__ __forceinline__ float fexp(float x){ return fx2(x*1.4426950408889634f); }
__device__ __forceinline__ float fsilu(float x){ return x/(1.f+fexp(-x)); }
__device__ __forceinline__ float to_tf32(float x){
    uint32_t u; asm("cvt.rna.tf32.f32 %0, %1;" : "=r"(u) : "f"(x));
    return __uint_as_float(u);
}

// ---------------- input projection: h = x @ in_w^T + in_b ----------------
__global__ void inproj_kernel(const float* __restrict__ x, const float* __restrict__ w,
                              const float* __restrict__ b){
    int idx = blockIdx.x*blockDim.x + threadIdx.x;
    if (idx >= MROWS*DMODEL) return;
    int m = idx / DMODEL, d = idx % DMODEL;
    const float* xr = x + m*DIN;
    const float* wr = w + d*DIN;
    float acc = b[d];
#pragma unroll
    for (int i = 0; i < DIN; i++) acc += xr[i]*wr[i];
    g_h[idx] = acc;
}

// ---------------- tf32 tensor-core NT GEMM ----------------
// C[m,n] = sum_k A[m,k]*B[n,k].  A row-major [M,K] (lda), B row-major [N,K] (ldb).
// BM=128, BN=64, BK=32, 256 threads (8 warps, 4x2 warp grid, 32x32 warp tile).
// Smem holds pre-permuted mma fragments (lane^p XOR swizzle → conflict-free).
// EPI: 0 = none, 1 = softplus(c + bias[n])
template<int EPI>
__global__ __launch_bounds__(256)
void gemm_tc(const float* __restrict__ A, const float* __restrict__ B, float* __restrict__ C,
             int K, int lda, int ldb, int ldc, const float* __restrict__ bias){
    constexpr int BM = 128, BN = 64, BK = 32;
    constexpr int NP = BK/8;     // 4 k8 panels
    constexpr int MB = BM/16;    // 8 m16 blocks
    constexpr int NB = BN/8;     // 8 n8 blocks
    constexpr int MM = 2;        // m16 mmas per warp
    constexpr int MN = 4;        // n8 mmas per warp
    constexpr int NA4 = BM*(BK/4)/256;   // 4 float4 A loads per thread
    constexpr int NB4 = BN*(BK/4)/256;   // 2 float4 B loads per thread

    __shared__ float As[2][NP*MB*128];
    __shared__ float Bs[2][NP*NB*64];

    const int tid  = threadIdx.x;
    const int wid  = tid >> 5, lane = tid & 31;
    const int wm   = wid & 3, wn = wid >> 2;
    const int row0 = blockIdx.y*BM;
    const int col0 = blockIdx.x*BN;
    const float* Ag = A + (size_t)row0*lda;
    const float* Bg = B + (size_t)col0*ldb;

    float acc[MM][MN][4];
#pragma unroll
    for (int i = 0; i < MM; i++)
#pragma unroll
        for (int j = 0; j < MN; j++)
#pragma unroll
            for (int q = 0; q < 4; q++) acc[i][j][q] = 0.f;

    float4 ra[NA4], rb[NB4];

    auto loadg = [&](int kt){
#pragma unroll
        for (int it = 0; it < NA4; it++){
            int i = it*256 + tid;
            int r = i >> 3, c4 = (i & 7)*4;
            ra[it] = *reinterpret_cast<const float4*>(Ag + (size_t)r*lda + kt + c4);
        }
#pragma unroll
        for (int it = 0; it < NB4; it++){
            int i = it*256 + tid;
            int n = i >> 3, c4 = (i & 7)*4;
            rb[it] = *reinterpret_cast<const float4*>(Bg + (size_t)n*ldb + kt + c4);
        }
    };
    auto stage = [&](int buf){
#pragma unroll
        for (int it = 0; it < NA4; it++){
            int i = it*256 + tid;
            int r = i >> 3, c4 = (i & 7)*4;
            int p = c4 >> 3, t0 = c4 & 7;
            int g = r & 15, mb = r >> 4;
            int L0 = (g & 7)*4;
            int slot = ((t0 >> 2) << 1) | (g >> 3);
            float* Ap = &As[buf][(p*MB + mb)*128];
            float v[4] = {ra[it].x, ra[it].y, ra[it].z, ra[it].w};
#pragma unroll
            for (int j = 0; j < 4; j++)
                Ap[(((L0 + j) ^ p) << 2) + slot] = to_tf32(v[j]);
        }
#pragma unroll
        for (int it = 0; it < NB4; it++){
            int i = it*256 + tid;
            int n = i >> 3, c4 = (i & 7)*4;
            int p = c4 >> 3, t0 = c4 & 7;
            int gn = n & 7, nb = n >> 3;
            int L0 = gn*4;
            int slot = t0 >> 2;
            float* Bp = &Bs[buf][(p*NB + nb)*64];
            float v[4] = {rb[it].x, rb[it].y, rb[it].z, rb[it].w};
#pragma unroll
            for (int j = 0; j < 4; j++)
                Bp[(((L0 + j) ^ p) << 1) + slot] = to_tf32(v[j]);
        }
    };
    auto compute = [&](int buf){
#pragma unroll
        for (int p = 0; p < NP; p++){
            uint32_t af[MM][4];
#pragma unroll
            for (int i = 0; i < MM; i++){
                float4 t = *reinterpret_cast<const float4*>(
                    &As[buf][(p*MB + wm*MM + i)*128 + ((lane ^ p) << 2)]);
                af[i][0] = __float_as_uint(t.x); af[i][1] = __float_as_uint(t.y);
                af[i][2] = __float_as_uint(t.z); af[i][3] = __float_as_uint(t.w);
            }
            uint32_t bf[MN][2];
#pragma unroll
            for (int j = 0; j < MN; j++){
                float2 t = *reinterpret_cast<const float2*>(
                    &Bs[buf][(p*NB + wn*MN + j)*64 + ((lane ^ p) << 1)]);
                bf[j][0] = __float_as_uint(t.x); bf[j][1] = __float_as_uint(t.y);
            }
#pragma unroll
            for (int i = 0; i < MM; i++)
#pragma unroll
                for (int j = 0; j < MN; j++){
                    asm volatile(
                        "mma.sync.aligned.m16n8k8.row.col.f32.tf32.tf32.f32 "
                        "{%0,%1,%2,%3}, {%4,%5,%6,%7}, {%8,%9}, {%0,%1,%2,%3};"
                        : "+f"(acc[i][j][0]), "+f"(acc[i][j][1]),
                          "+f"(acc[i][j][2]), "+f"(acc[i][j][3])
                        : "r"(af[i][0]), "r"(af[i][1]), "r"(af[i][2]), "r"(af[i][3]),
                          "r"(bf[j][0]), "r"(bf[j][1]));
                }
        }
    };

    const int nk = K / BK;
    loadg(0);
    stage(0);
    __syncthreads();
    int buf = 0;
    for (int t = 0; t < nk; t++){
        if (t + 1 < nk) loadg((t+1)*BK);
        compute(buf);
        if (t + 1 < nk) stage(buf ^ 1);
        __syncthreads();
        buf ^= 1;
    }

#pragma unroll
    for (int i = 0; i < MM; i++){
#pragma unroll
        for (int j = 0; j < MN; j++){
            int gr = row0 + wm*32 + i*16 + (lane >> 2);
            int gc = col0 + wn*32 + j*8  + (lane & 3)*2;
            float v0 = acc[i][j][0], v1 = acc[i][j][1];
            float v2 = acc[i][j][2], v3 = acc[i][j][3];
            if (EPI == 1){
                float b0 = bias[gc], b1 = bias[gc+1];
                v0 += b0; v1 += b1; v2 += b0; v3 += b1;
                v0 = (v0 > 20.f) ? v0 : log1pf(fexp(v0));
                v1 = (v1 > 20.f) ? v1 : log1pf(fexp(v1));
                v2 = (v2 > 20.f) ? v2 : log1pf(fexp(v2));
                v3 = (v3 > 20.f) ? v3 : log1pf(fexp(v3));
            }
            *reinterpret_cast<float2*>(&C[(size_t)gr*ldc + gc])     = make_float2(v0, v1);
            *reinterpret_cast<float2*>(&C[(size_t)(gr+8)*ldc + gc]) = make_float2(v2, v3);
        }
    }
}

// ---------------- causal conv1d + silu, plus silu(z) ----------------
__global__ void conv_silu_kernel(const float* __restrict__ cw, const float* __restrict__ cb){
    int idx = blockIdx.x*blockDim.x + threadIdx.x;
    if (idx >= MROWS*DINNER) return;
    int r = idx / DINNER, e = idx % DINNER;
    int b = r / LL, l = r % LL;
    float acc = cb[e];
#pragma unroll
    for (int k = 0; k < DCONV; k++){
        int lp = l - (DCONV-1) + k;
        if (lp >= 0)
            acc += cw[e*DCONV + k] * g_xz[((size_t)(b*LL + lp))*(2*DINNER) + e];
    }
    g_u[idx] = fsilu(acc);
    float z = g_xz[(size_t)r*(2*DINNER) + DINNER + e];
    g_sz[idx] = fsilu(z);
}

// ---------------- selective scan: 4 lanes per channel (4 states each) ----------------
// grid (DINNER/32, BB) = 128 blocks, 128 threads.
// Warp covers 8 channels x 4 state-quarters; y reduced via 2x shfl_xor.
__global__ __launch_bounds__(128)
void scan_kernel(const float* __restrict__ A_log, const float* __restrict__ Dp){
    const int b = blockIdx.y;
    const int w = threadIdx.x >> 5, lane = threadIdx.x & 31;
    const int d  = blockIdx.x*32 + w*8 + (lane & 7);
    const int sq = lane >> 3;             // state quarter 0..3

    float a2[4];
#pragma unroll
    for (int k = 0; k < 4; k++)
        a2[k] = -expf(A_log[d*DSTATE + sq*4 + k]) * 1.4426950408889634f;
    const float dp = Dp[d];

    float st[4] = {0.f, 0.f, 0.f, 0.f};
    __shared__ float sBC[64][32];   // 64 timesteps of [B(16) | C(16)]

    for (int t0 = 0; t0 < LL; t0 += 64){
        for (int i = threadIdx.x; i < 64*32; i += 128){
            int tt = i >> 5, j = i & 31;
            sBC[tt][j] = g_xdbl[((size_t)(b*LL + t0 + tt))*64 + DTRANK + j];
        }
        __syncthreads();
#pragma unroll 4
        for (int tt = 0; tt < 64; tt++){
            size_t idx = ((size_t)(b*LL + t0 + tt))*DINNER + d;
            float dt = g_dt[idx];
            float uu = g_u[idx];
            float du = dt*uu;
            float y = 0.f;
#pragma unroll
            for (int k = 0; k < 4; k++){
                float dA = fx2(dt*a2[k]);
                st[k] = dA*st[k] + sBC[tt][sq*4 + k]*du;
                y += st[k]*sBC[tt][16 + sq*4 + k];
            }
            y += __shfl_xor_sync(0xffffffffu, y, 8);
            y += __shfl_xor_sync(0xffffffffu, y, 16);
            if (sq == 0){
                g_y[idx] = (y + uu*dp) * g_sz[idx];
            }
        }
        __syncthreads();
    }
}

// ---------------- final layernorm ----------------
__global__ __launch_bounds__(128)
void ln_kernel(const float* __restrict__ gamma, const float* __restrict__ beta,
               float* __restrict__ out){
    const int m = blockIdx.x;
    const int tid = threadIdx.x;
    const float4 v = reinterpret_cast<const float4*>(g_h + (size_t)m*DMODEL)[tid];
    float s  = v.x + v.y + v.z + v.w;
    float sq = v.x*v.x + v.y*v.y + v.z*v.z + v.w*v.w;
#pragma unroll
    for (int off = 16; off; off >>= 1){
        s  += __shfl_xor_sync(0xffffffffu, s,  off);
        sq += __shfl_xor_sync(0xffffffffu, sq, off);
    }
    __shared__ float r1[4], r2[4];
    if ((tid & 31) == 0){ r1[tid>>5] = s; r2[tid>>5] = sq; }
    __syncthreads();
    s  = r1[0] + r1[1] + r1[2] + r1[3];
    sq = r2[0] + r2[1] + r2[2] + r2[3];
    float mu  = s * (1.f/DMODEL);
    float var = sq * (1.f/DMODEL) - mu*mu;
    float rs  = rsqrtf(var + 1e-5f);
    float4 g4 = reinterpret_cast<const float4*>(gamma)[tid];
    float4 b4 = reinterpret_cast<const float4*>(beta)[tid];
    float4 o;
    o.x = (v.x - mu)*rs*g4.x + b4.x;
    o.y = (v.y - mu)*rs*g4.y + b4.y;
    o.z = (v.z - mu)*rs*g4.z + b4.z;
    o.w = (v.w - mu)*rs*g4.w + b4.w;
    reinterpret_cast<float4*>(out + (size_t)m*DMODEL)[tid] = o;
}

// ---------------- launch ----------------
extern "C" void kernel_launch(void* const* d_in, const int* in_sizes, int n_in,
                              void* d_out, int out_size){
    const float* x       = (const float*)d_in[0];
    const float* in_w    = (const float*)d_in[1];
    const float* in_b    = (const float*)d_in[2];
    const float* W_xz    = (const float*)d_in[3];
    const float* conv_w  = (const float*)d_in[4];
    const float* conv_b  = (const float*)d_in[5];
    const float* W_xp    = (const float*)d_in[6];
    const float* W_dt    = (const float*)d_in[7];
    const float* b_dt    = (const float*)d_in[8];
    const float* A_log   = (const float*)d_in[9];
    const float* D_param = (const float*)d_in[10];
    const float* W_out   = (const float*)d_in[11];
    const float* ln_g    = (const float*)d_in[12];
    const float* ln_b    = (const float*)d_in[13];
    float* out = (float*)d_out;

    float *ph, *pxz, *pu, *pxdbl, *pdt, *py;
    cudaGetSymbolAddress((void**)&ph,    g_h);
    cudaGetSymbolAddress((void**)&pxz,   g_xz);
    cudaGetSymbolAddress((void**)&pu,    g_u);
    cudaGetSymbolAddress((void**)&pxdbl, g_xdbl);
    cudaGetSymbolAddress((void**)&pdt,   g_dt);
    cudaGetSymbolAddress((void**)&py,    g_y);

    inproj_kernel<<<(MROWS*DMODEL)/128, 128>>>(x, in_w, in_b);

    for (int lyr = 0; lyr < NDEPTH; lyr++){
        // xz = h @ Wxz^T           M=4096 N=2048 K=512
        gemm_tc<0><<<dim3(2048/64, MROWS/128), 256>>>(
            ph, W_xz + (size_t)lyr*2048*DMODEL, pxz,
            DMODEL, DMODEL, DMODEL, 2*DINNER, nullptr);

        conv_silu_kernel<<<(MROWS*DINNER)/256, 256>>>(
            conv_w + (size_t)lyr*DINNER*DCONV, conv_b + (size_t)lyr*DINNER);

        // xdbl = u @ Wxp^T         M=4096 N=64 K=1024
        gemm_tc<0><<<dim3(1, MROWS/128), 256>>>(
            pu, W_xp + (size_t)lyr*64*DINNER, pxdbl,
            DINNER, DINNER, DINNER, 64, nullptr);

        // dt = softplus(dt_lr @ Wdt^T + b_dt)   M=4096 N=1024 K=32 (lda=64)
        gemm_tc<1><<<dim3(DINNER/64, MROWS/128), 256>>>(
            pxdbl, W_dt + (size_t)lyr*DINNER*DTRANK, pdt,
            DTRANK, 64, DTRANK, DINNER, b_dt + (size_t)lyr*DINNER);

        scan_kernel<<<dim3(DINNER/32, BB), 128>>>(
            A_log + (size_t)lyr*DINNER*DSTATE, D_param + (size_t)lyr*DINNER);

        // h = y @ Wout^T           M=4096 N=512 K=1024
        gemm_tc<0><<<dim3(DMODEL/64, MROWS/128), 256>>>(
            py, W_out + (size_t)lyr*DMODEL*DINNER, ph,
            DINNER, DINNER, DINNER, DMODEL, nullptr);
    }

    ln_kernel<<<MROWS, 128>>>(ln_g, ln_b, out);
}

// round 5
// speedup vs baseline: 1.4886x; 1.2687x over previous
#include <cuda_runtime.h>
#include <cuda_fp16.h>
#include <cstdio>
#include <cstdint>

#define BB 4
#define LL 1024
#define DIN 8
#define DMODEL 512
#define NDEPTH 4
#define DINNER 1024
#define DSTATE 16
#define DCONV 4
#define DTRANK 32
#define MROWS (BB*LL)   /* 4096 */

// ---------------- scratch ----------------
__device__ float  g_h[MROWS*DMODEL];
__device__ float  g_xz[MROWS*2*DINNER];
__device__ float  g_u[MROWS*DINNER];
__device__ float  g_sz[MROWS*DINNER];
__device__ float  g_xdbl[MROWS*64];
__device__ float  g_dt[MROWS*DINNER];
__device__ float  g_part[4*MROWS*64];        // split-K partials for xp gemm

__device__ __half g_h16[MROWS*DMODEL];
__device__ __half g_u16[MROWS*DINNER];
__device__ __half g_y16[MROWS*DINNER];
__device__ __half g_dtlr16[MROWS*DTRANK];
__device__ __half g_w16[6684672];            // fp16 weight arena

// weight arena offsets (elements)
#define OFF_XZ  0
#define SZ_XZ_L (2048*512)
#define OFF_XP  4194304
#define SZ_XP_L (64*1024)
#define OFF_DT  4456448
#define SZ_DT_L (1024*32)
#define OFF_OUT 4587520
#define SZ_OUT_L (512*1024)

// ---------------- helpers ----------------
__device__ __forceinline__ float fx2(float x){ float y; asm("ex2.approx.f32 %0,%1;" : "=f"(y) : "f"(x)); return y; }
__device__ __forceinline__ float fexp(float x){ return fx2(x*1.4426950408889634f); }
__device__ __forceinline__ float fsilu(float x){ return x/(1.f+fexp(-x)); }
__device__ __forceinline__ uint32_t smem_u32(const void* p){
    uint32_t a; asm("{ .reg .u64 t; cvta.to.shared.u64 t, %1; cvt.u32.u64 %0, t; }" : "=r"(a) : "l"(p));
    return a;
}

#define LDSM4(r0,r1,r2,r3,addr) \
    asm volatile("ldmatrix.sync.aligned.m8n8.x4.shared.b16 {%0,%1,%2,%3}, [%4];" \
        : "=r"(r0),"=r"(r1),"=r"(r2),"=r"(r3) : "r"(addr))

#define MMA16816(d, a, b) \
    asm volatile("mma.sync.aligned.m16n8k16.row.col.f32.f16.f16.f32 " \
        "{%0,%1,%2,%3}, {%4,%5,%6,%7}, {%8,%9}, {%0,%1,%2,%3};" \
        : "+f"((d)[0]), "+f"((d)[1]), "+f"((d)[2]), "+f"((d)[3]) \
        : "r"((a)[0]), "r"((a)[1]), "r"((a)[2]), "r"((a)[3]), \
          "r"((b)[0]), "r"((b)[1]))

#define CP_ASYNC16(saddr, gptr) \
    asm volatile("cp.async.cg.shared.global [%0], [%1], 16;" :: "r"(saddr), "l"(gptr))
#define CP_COMMIT() asm volatile("cp.async.commit_group;")
#define CP_WAIT(n)  asm volatile("cp.async.wait_group %0;" :: "n"(n))

// ---------------- fp32 -> fp16 conversion ----------------
__global__ void f2h_kernel(const float* __restrict__ s, __half* __restrict__ d, int n4){
    int i = blockIdx.x*blockDim.x + threadIdx.x;
    if (i >= n4) return;
    float4 v = reinterpret_cast<const float4*>(s)[i];
    __half2* o = reinterpret_cast<__half2*>(d);
    o[2*i]   = __floats2half2_rn(v.x, v.y);
    o[2*i+1] = __floats2half2_rn(v.z, v.w);
}

// ---------------- input projection ----------------
__global__ void inproj_kernel(const float* __restrict__ x, const float* __restrict__ w,
                              const float* __restrict__ b){
    int idx = blockIdx.x*blockDim.x + threadIdx.x;
    if (idx >= MROWS*DMODEL) return;
    int m = idx / DMODEL, d = idx % DMODEL;
    const float* xr = x + m*DIN;
    const float* wr = w + d*DIN;
    float acc = b[d];
#pragma unroll
    for (int i = 0; i < DIN; i++) acc += xr[i]*wr[i];
    g_h[idx] = acc;
    g_h16[idx] = __float2half(acc);
}

// ---------------- fp16 tensor-core NT GEMM ----------------
// C[m,n] = sum_k A[m,k]*B[n,k], A [M,K] fp16 row-major, B [N,K] fp16 row-major.
// BM=128, BN template (128|64), BK=32, 256 threads (8 warps, 4m x 2n).
// 4-stage cp.async pipeline, ldmatrix frags, fp32 accum.
// EPI: 0 none | 1 softplus(c+bias[n]) | 2 dual-write fp32 C + fp16 C16.
// Split-K via gridDim.z; partials at C + bz*partStride.
template<int BN, int EPI>
__global__ __launch_bounds__(256, 2)
void gemm_h(const __half* __restrict__ A, const __half* __restrict__ B, float* __restrict__ C,
            int K, int lda, int ldb, int ldc, const float* __restrict__ bias,
            __half* __restrict__ C16, int ldc16, int partStride)
{
    constexpr int BM = 128, BK = 32, STG = 4;
    constexpr int NW  = BN/2;          // warp n extent
    constexpr int NFR = NW/8;          // n8 frags per warp
    constexpr int ROWB = 80;           // 64B data + 16B pad (conflict-free LDSM)
    constexpr int ABYTES = BM*ROWB;
    constexpr int BBYTES = BN*ROWB;
    constexpr int STGB = ABYTES + BBYTES;

    extern __shared__ char smem[];
    const uint32_t sb = smem_u32(smem);
    const int tid = threadIdx.x, wid = tid >> 5, lane = tid & 31;
    const int wm = wid & 3, wn = wid >> 2;
    const int row0 = blockIdx.y*BM, col0 = blockIdx.x*BN;
    const int kslice = K / gridDim.z;
    const int k0 = blockIdx.z * kslice;
    const int ntiles = kslice / BK;

    const __half* Ag = A + (size_t)row0*lda + k0;
    const __half* Bg = B + (size_t)col0*ldb + k0;
    float* Cp = C + (size_t)blockIdx.z * partStride;

    float acc[2][NFR][4];
#pragma unroll
    for (int i = 0; i < 2; i++)
#pragma unroll
        for (int j = 0; j < NFR; j++)
#pragma unroll
            for (int q = 0; q < 4; q++) acc[i][j][q] = 0.f;

    auto issue = [&](int t){
        int buf = t & (STG-1);
        uint32_t as = sb + buf*STGB;
        uint32_t bs = as + ABYTES;
        int kt = t*BK;
#pragma unroll
        for (int it = 0; it < 2; it++){
            int i = it*256 + tid;
            int r = i >> 2, c = i & 3;
            CP_ASYNC16(as + r*ROWB + c*16, Ag + (size_t)r*lda + kt + c*8);
        }
#pragma unroll
        for (int it = 0; it < BN/64; it++){
            int i = it*256 + tid;
            int r = i >> 2, c = i & 3;
            CP_ASYNC16(bs + r*ROWB + c*16, Bg + (size_t)r*ldb + kt + c*8);
        }
    };

    auto compute = [&](int t){
        int buf = t & (STG-1);
        uint32_t as = sb + buf*STGB + wm*32*ROWB;
        uint32_t bs = sb + buf*STGB + ABYTES + wn*NW*ROWB;
#pragma unroll
        for (int s = 0; s < 2; s++){
            uint32_t a[2][4];
#pragma unroll
            for (int im = 0; im < 2; im++){
                uint32_t addr = as + (im*16 + (lane & 7) + ((lane >> 3) & 1)*8)*ROWB
                              + (2*s + (lane >> 4))*16;
                LDSM4(a[im][0], a[im][1], a[im][2], a[im][3], addr);
            }
            uint32_t b[NFR][2];
#pragma unroll
            for (int j = 0; j < NFR/2; j++){
                uint32_t addr = bs + (j*16 + (lane & 7) + (lane >> 4)*8)*ROWB
                              + (2*s + ((lane >> 3) & 1))*16;
                LDSM4(b[2*j][0], b[2*j][1], b[2*j+1][0], b[2*j+1][1], addr);
            }
#pragma unroll
            for (int im = 0; im < 2; im++)
#pragma unroll
                for (int j = 0; j < NFR; j++)
                    MMA16816(acc[im][j], a[im], b[j]);
        }
    };

#pragma unroll
    for (int i = 0; i < STG-1; i++){
        if (i < ntiles){ issue(i); CP_COMMIT(); }
    }
    for (int t = 0; t < ntiles; t++){
        if (t + STG-1 <= ntiles - 1 + 1 && t + (STG-1) <= ntiles){ CP_WAIT(STG-2); }
        else { CP_WAIT(0); }
        __syncthreads();
        if (t + STG-1 < ntiles){ issue(t + STG-1); CP_COMMIT(); }
        compute(t);
        __syncthreads();
    }

    // epilogue
#pragma unroll
    for (int im = 0; im < 2; im++){
        int r = row0 + wm*32 + im*16 + (lane >> 2);
#pragma unroll
        for (int j = 0; j < NFR; j++){
            int c = col0 + wn*NW + j*8 + (lane & 3)*2;
            float v0 = acc[im][j][0], v1 = acc[im][j][1];
            float v2 = acc[im][j][2], v3 = acc[im][j][3];
            if (EPI == 1){
                float b0 = bias[c], b1 = bias[c+1];
                v0 += b0; v1 += b1; v2 += b0; v3 += b1;
                v0 = (v0 > 20.f) ? v0 : log1pf(fexp(v0));
                v1 = (v1 > 20.f) ? v1 : log1pf(fexp(v1));
                v2 = (v2 > 20.f) ? v2 : log1pf(fexp(v2));
                v3 = (v3 > 20.f) ? v3 : log1pf(fexp(v3));
            }
            *reinterpret_cast<float2*>(&Cp[(size_t)r*ldc + c])     = make_float2(v0, v1);
            *reinterpret_cast<float2*>(&Cp[(size_t)(r+8)*ldc + c]) = make_float2(v2, v3);
            if (EPI == 2){
                *reinterpret_cast<__half2*>(&C16[(size_t)r*ldc16 + c])     = __floats2half2_rn(v0, v1);
                *reinterpret_cast<__half2*>(&C16[(size_t)(r+8)*ldc16 + c]) = __floats2half2_rn(v2, v3);
            }
        }
    }
}

// ---------------- split-K reduce for xp gemm ----------------
__global__ void reduce_xp_kernel(){
    int idx = blockIdx.x*blockDim.x + threadIdx.x;
    if (idx >= MROWS*64) return;
    float s = g_part[idx] + g_part[MROWS*64 + idx]
            + g_part[2*MROWS*64 + idx] + g_part[3*MROWS*64 + idx];
    g_xdbl[idx] = s;
    int col = idx & 63;
    if (col < DTRANK){
        int row = idx >> 6;
        g_dtlr16[row*DTRANK + col] = __float2half(s);
    }
}

// ---------------- causal conv1d + silu, plus silu(z) ----------------
__global__ void conv_silu_kernel(const float* __restrict__ cw, const float* __restrict__ cb){
    int idx = blockIdx.x*blockDim.x + threadIdx.x;
    if (idx >= MROWS*DINNER) return;
    int r = idx / DINNER, e = idx % DINNER;
    int b = r / LL, l = r % LL;
    float acc = cb[e];
#pragma unroll
    for (int k = 0; k < DCONV; k++){
        int lp = l - (DCONV-1) + k;
        if (lp >= 0)
            acc += cw[e*DCONV + k] * g_xz[((size_t)(b*LL + lp))*(2*DINNER) + e];
    }
    float u = fsilu(acc);
    g_u[idx] = u;
    g_u16[idx] = __float2half(u);
    float z = g_xz[(size_t)r*(2*DINNER) + DINNER + e];
    g_sz[idx] = fsilu(z);
}

// ---------------- selective scan ----------------
__global__ __launch_bounds__(128)
void scan_kernel(const float* __restrict__ A_log, const float* __restrict__ Dp){
    const int b = blockIdx.y;
    const int w = threadIdx.x >> 5, lane = threadIdx.x & 31;
    const int d  = blockIdx.x*32 + w*8 + (lane & 7);
    const int sq = lane >> 3;

    float a2[4];
#pragma unroll
    for (int k = 0; k < 4; k++)
        a2[k] = -expf(A_log[d*DSTATE + sq*4 + k]) * 1.4426950408889634f;
    const float dp = Dp[d];

    float st[4] = {0.f, 0.f, 0.f, 0.f};
    __shared__ float sBC[64][32];

    for (int t0 = 0; t0 < LL; t0 += 64){
        for (int i = threadIdx.x; i < 64*32; i += 128){
            int tt = i >> 5, j = i & 31;
            sBC[tt][j] = g_xdbl[((size_t)(b*LL + t0 + tt))*64 + DTRANK + j];
        }
        __syncthreads();
#pragma unroll 4
        for (int tt = 0; tt < 64; tt++){
            size_t idx = ((size_t)(b*LL + t0 + tt))*DINNER + d;
            float dt = g_dt[idx];
            float uu = g_u[idx];
            float du = dt*uu;
            float y = 0.f;
#pragma unroll
            for (int k = 0; k < 4; k++){
                float dA = fx2(dt*a2[k]);
                st[k] = dA*st[k] + sBC[tt][sq*4 + k]*du;
                y += st[k]*sBC[tt][16 + sq*4 + k];
            }
            y += __shfl_xor_sync(0xffffffffu, y, 8);
            y += __shfl_xor_sync(0xffffffffu, y, 16);
            if (sq == 0){
                g_y16[idx] = __float2half((y + uu*dp) * g_sz[idx]);
            }
        }
        __syncthreads();
    }
}

// ---------------- final layernorm ----------------
__global__ __launch_bounds__(128)
void ln_kernel(const float* __restrict__ gamma, const float* __restrict__ beta,
               float* __restrict__ out){
    const int m = blockIdx.x;
    const int tid = threadIdx.x;
    const float4 v = reinterpret_cast<const float4*>(g_h + (size_t)m*DMODEL)[tid];
    float s  = v.x + v.y + v.z + v.w;
    float sq = v.x*v.x + v.y*v.y + v.z*v.z + v.w*v.w;
#pragma unroll
    for (int off = 16; off; off >>= 1){
        s  += __shfl_xor_sync(0xffffffffu, s,  off);
        sq += __shfl_xor_sync(0xffffffffu, sq, off);
    }
    __shared__ float r1[4], r2[4];
    if ((tid & 31) == 0){ r1[tid>>5] = s; r2[tid>>5] = sq; }
    __syncthreads();
    s  = r1[0] + r1[1] + r1[2] + r1[3];
    sq = r2[0] + r2[1] + r2[2] + r2[3];
    float mu  = s * (1.f/DMODEL);
    float var = sq * (1.f/DMODEL) - mu*mu;
    float rs  = rsqrtf(var + 1e-5f);
    float4 g4 = reinterpret_cast<const float4*>(gamma)[tid];
    float4 b4 = reinterpret_cast<const float4*>(beta)[tid];
    float4 o;
    o.x = (v.x - mu)*rs*g4.x + b4.x;
    o.y = (v.y - mu)*rs*g4.y + b4.y;
    o.z = (v.z - mu)*rs*g4.z + b4.z;
    o.w = (v.w - mu)*rs*g4.w + b4.w;
    reinterpret_cast<float4*>(out + (size_t)m*DMODEL)[tid] = o;
}

// ---------------- launch ----------------
extern "C" void kernel_launch(void* const* d_in, const int* in_sizes, int n_in,
                              void* d_out, int out_size){
    const float* x       = (const float*)d_in[0];
    const float* in_w    = (const float*)d_in[1];
    const float* in_b    = (const float*)d_in[2];
    const float* W_xz    = (const float*)d_in[3];
    const float* conv_w  = (const float*)d_in[4];
    const float* conv_b  = (const float*)d_in[5];
    const float* W_xp    = (const float*)d_in[6];
    const float* W_dt    = (const float*)d_in[7];
    const float* b_dt    = (const float*)d_in[8];
    const float* A_log   = (const float*)d_in[9];
    const float* D_param = (const float*)d_in[10];
    const float* W_out   = (const float*)d_in[11];
    const float* ln_g    = (const float*)d_in[12];
    const float* ln_b    = (const float*)d_in[13];
    float* out = (float*)d_out;

    float *ph, *pxz, *pdt, *ppart;
    __half *ph16, *pu16, *py16, *pdtlr16, *pw16;
    cudaGetSymbolAddress((void**)&ph,     g_h);
    cudaGetSymbolAddress((void**)&pxz,    g_xz);
    cudaGetSymbolAddress((void**)&pdt,    g_dt);
    cudaGetSymbolAddress((void**)&ppart,  g_part);
    cudaGetSymbolAddress((void**)&ph16,   g_h16);
    cudaGetSymbolAddress((void**)&pu16,   g_u16);
    cudaGetSymbolAddress((void**)&py16,   g_y16);
    cudaGetSymbolAddress((void**)&pdtlr16,g_dtlr16);
    cudaGetSymbolAddress((void**)&pw16,   g_w16);

    const int SM128 = 4*(128*80 + 128*80);   // 81920
    const int SM64  = 4*(128*80 + 64*80);    // 61440
    cudaFuncSetAttribute(gemm_h<128,0>, cudaFuncAttributeMaxDynamicSharedMemorySize, SM128);
    cudaFuncSetAttribute(gemm_h<128,1>, cudaFuncAttributeMaxDynamicSharedMemorySize, SM128);
    cudaFuncSetAttribute(gemm_h<128,2>, cudaFuncAttributeMaxDynamicSharedMemorySize, SM128);
    cudaFuncSetAttribute(gemm_h<64,0>,  cudaFuncAttributeMaxDynamicSharedMemorySize, SM64);

    // weight conversions (fp32 -> fp16 arena)
    f2h_kernel<<<(NDEPTH*SZ_XZ_L/4 + 255)/256, 256>>>(W_xz,  pw16 + OFF_XZ,  NDEPTH*SZ_XZ_L/4);
    f2h_kernel<<<(NDEPTH*SZ_XP_L/4 + 255)/256, 256>>>(W_xp,  pw16 + OFF_XP,  NDEPTH*SZ_XP_L/4);
    f2h_kernel<<<(NDEPTH*SZ_DT_L/4 + 255)/256, 256>>>(W_dt,  pw16 + OFF_DT,  NDEPTH*SZ_DT_L/4);
    f2h_kernel<<<(NDEPTH*SZ_OUT_L/4 + 255)/256, 256>>>(W_out, pw16 + OFF_OUT, NDEPTH*SZ_OUT_L/4);

    inproj_kernel<<<(MROWS*DMODEL)/128, 128>>>(x, in_w, in_b);

    for (int lyr = 0; lyr < NDEPTH; lyr++){
        // xz = h @ Wxz^T      M=4096 N=2048 K=512
        gemm_h<128,0><<<dim3(2048/128, MROWS/128, 1), 256, SM128>>>(
            ph16, pw16 + OFF_XZ + (size_t)lyr*SZ_XZ_L, pxz,
            DMODEL, DMODEL, DMODEL, 2*DINNER, nullptr, nullptr, 0, 0);

        conv_silu_kernel<<<(MROWS*DINNER)/256, 256>>>(
            conv_w + (size_t)lyr*DINNER*DCONV, conv_b + (size_t)lyr*DINNER);

        // xdbl = u @ Wxp^T    M=4096 N=64 K=1024, split-K=4
        gemm_h<64,0><<<dim3(1, MROWS/128, 4), 256, SM64>>>(
            pu16, pw16 + OFF_XP + (size_t)lyr*SZ_XP_L, ppart,
            DINNER, DINNER, DINNER, 64, nullptr, nullptr, 0, MROWS*64);

        reduce_xp_kernel<<<(MROWS*64)/256, 256>>>();

        // dt = softplus(dt_lr @ Wdt^T + b_dt)   M=4096 N=1024 K=32
        gemm_h<128,1><<<dim3(DINNER/128, MROWS/128, 1), 256, SM128>>>(
            pdtlr16, pw16 + OFF_DT + (size_t)lyr*SZ_DT_L, pdt,
            DTRANK, DTRANK, DTRANK, DINNER, b_dt + (size_t)lyr*DINNER, nullptr, 0, 0);

        scan_kernel<<<dim3(DINNER/32, BB), 128>>>(
            A_log + (size_t)lyr*DINNER*DSTATE, D_param + (size_t)lyr*DINNER);

        // h = y @ Wout^T      M=4096 N=512 K=1024  (dual write fp32 + fp16)
        gemm_h<128,2><<<dim3(DMODEL/128, MROWS/128, 1), 256, SM128>>>(
            py16, pw16 + OFF_OUT + (size_t)lyr*SZ_OUT_L, ph,
            DINNER, DINNER, DINNER, DMODEL, nullptr, ph16, DMODEL, 0);
    }

    ln_kernel<<<MROWS, 128>>>(ln_g, ln_b, out);
}

// round 6
// speedup vs baseline: 1.4987x; 1.0068x over previous
#include <cuda_runtime.h>
#include <cuda_fp16.h>
#include <cstdio>
#include <cstdint>

#define BB 4
#define LL 1024
#define DIN 8
#define DMODEL 512
#define NDEPTH 4
#define DINNER 1024
#define DSTATE 16
#define DCONV 4
#define DTRANK 32
#define MROWS (BB*LL)   /* 4096 */

// ---------------- scratch ----------------
__device__ float  g_h[MROWS*DMODEL];
__device__ float  g_xz[MROWS*2*DINNER];
__device__ float  g_u[MROWS*DINNER];
__device__ float  g_sz[MROWS*DINNER];
__device__ float  g_xdbl[MROWS*64];
__device__ float  g_dt[MROWS*DINNER];
__device__ float  g_part[4*MROWS*64];        // split-K partials for xp gemm

__device__ __half g_h16[MROWS*DMODEL];
__device__ __half g_u16[MROWS*DINNER];
__device__ __half g_y16[MROWS*DINNER];
__device__ __half g_dtlr16[MROWS*DTRANK];
__device__ __half g_w16[6684672];            // fp16 weight arena

// weight arena offsets (elements)
#define OFF_XZ  0
#define SZ_XZ_L (2048*512)
#define OFF_XP  4194304
#define SZ_XP_L (64*1024)
#define OFF_DT  4456448
#define SZ_DT_L (1024*32)
#define OFF_OUT 4587520
#define SZ_OUT_L (512*1024)

// ---------------- helpers ----------------
__device__ __forceinline__ float fx2(float x){ float y; asm("ex2.approx.f32 %0,%1;" : "=f"(y) : "f"(x)); return y; }
__device__ __forceinline__ float fexp(float x){ return fx2(x*1.4426950408889634f); }
__device__ __forceinline__ float fsilu(float x){ return x/(1.f+fexp(-x)); }
__device__ __forceinline__ uint32_t smem_u32(const void* p){
    uint32_t a; asm("{ .reg .u64 t; cvta.to.shared.u64 t, %1; cvt.u32.u64 %0, t; }" : "=r"(a) : "l"(p));
    return a;
}

#define LDSM4(r0,r1,r2,r3,addr) \
    asm volatile("ldmatrix.sync.aligned.m8n8.x4.shared.b16 {%0,%1,%2,%3}, [%4];" \
        : "=r"(r0),"=r"(r1),"=r"(r2),"=r"(r3) : "r"(addr))

#define MMA16816(d, a, b) \
    asm volatile("mma.sync.aligned.m16n8k16.row.col.f32.f16.f16.f32 " \
        "{%0,%1,%2,%3}, {%4,%5,%6,%7}, {%8,%9}, {%0,%1,%2,%3};" \
        : "+f"((d)[0]), "+f"((d)[1]), "+f"((d)[2]), "+f"((d)[3]) \
        : "r"((a)[0]), "r"((a)[1]), "r"((a)[2]), "r"((a)[3]), \
          "r"((b)[0]), "r"((b)[1]))

#define CP_ASYNC16(saddr, gptr) \
    asm volatile("cp.async.cg.shared.global [%0], [%1], 16;" :: "r"(saddr), "l"(gptr))
#define CP_COMMIT() asm volatile("cp.async.commit_group;")
#define CP_WAIT(n)  asm volatile("cp.async.wait_group %0;" :: "n"(n))

// ---------------- fp32 -> fp16 conversion ----------------
__global__ void f2h_kernel(const float* __restrict__ s, __half* __restrict__ d, int n4){
    int i = blockIdx.x*blockDim.x + threadIdx.x;
    if (i >= n4) return;
    float4 v = reinterpret_cast<const float4*>(s)[i];
    __half2* o = reinterpret_cast<__half2*>(d);
    o[2*i]   = __floats2half2_rn(v.x, v.y);
    o[2*i+1] = __floats2half2_rn(v.z, v.w);
}

// ---------------- input projection ----------------
__global__ void inproj_kernel(const float* __restrict__ x, const float* __restrict__ w,
                              const float* __restrict__ b){
    int idx = blockIdx.x*blockDim.x + threadIdx.x;
    if (idx >= MROWS*DMODEL) return;
    int m = idx / DMODEL, d = idx % DMODEL;
    const float* xr = x + m*DIN;
    const float* wr = w + d*DIN;
    float acc = b[d];
#pragma unroll
    for (int i = 0; i < DIN; i++) acc += xr[i]*wr[i];
    g_h[idx] = acc;
    g_h16[idx] = __float2half(acc);
}

// ---------------- fp16 tensor-core NT GEMM ----------------
// C[m,n] = sum_k A[m,k]*B[n,k]. BM=128, BN template, BK=32, 256 thr, 4-stage
// cp.async, single barrier per k-tile, exact tail waits.
// EPI: 0 none | 1 softplus(c+bias[n]) | 2 dual-write fp32 C + fp16 C16.
template<int BN, int EPI>
__global__ __launch_bounds__(256, 2)
void gemm_h(const __half* __restrict__ A, const __half* __restrict__ B, float* __restrict__ C,
            int K, int lda, int ldb, int ldc, const float* __restrict__ bias,
            __half* __restrict__ C16, int ldc16, int partStride)
{
    constexpr int BM = 128, BK = 32, STG = 4;
    constexpr int NW  = BN/2;
    constexpr int NFR = NW/8;
    constexpr int ROWB = 80;           // 64B data + 16B pad
    constexpr int ABYTES = BM*ROWB;
    constexpr int BBYTES = BN*ROWB;
    constexpr int STGB = ABYTES + BBYTES;

    extern __shared__ char smem[];
    const uint32_t sb = smem_u32(smem);
    const int tid = threadIdx.x, wid = tid >> 5, lane = tid & 31;
    const int wm = wid & 3, wn = wid >> 2;
    const int row0 = blockIdx.y*BM, col0 = blockIdx.x*BN;
    const int kslice = K / gridDim.z;
    const int k0 = blockIdx.z * kslice;
    const int ntiles = kslice / BK;

    const __half* Ag = A + (size_t)row0*lda + k0;
    const __half* Bg = B + (size_t)col0*ldb + k0;
    float* Cp = C + (size_t)blockIdx.z * partStride;

    float acc[2][NFR][4];
#pragma unroll
    for (int i = 0; i < 2; i++)
#pragma unroll
        for (int j = 0; j < NFR; j++)
#pragma unroll
            for (int q = 0; q < 4; q++) acc[i][j][q] = 0.f;

    auto issue = [&](int t){
        int buf = t & (STG-1);
        uint32_t as = sb + buf*STGB;
        uint32_t bs = as + ABYTES;
        int kt = t*BK;
#pragma unroll
        for (int it = 0; it < 2; it++){
            int i = it*256 + tid;
            int r = i >> 2, c = i & 3;
            CP_ASYNC16(as + r*ROWB + c*16, Ag + (size_t)r*lda + kt + c*8);
        }
#pragma unroll
        for (int it = 0; it < BN/64; it++){
            int i = it*256 + tid;
            int r = i >> 2, c = i & 3;
            CP_ASYNC16(bs + r*ROWB + c*16, Bg + (size_t)r*ldb + kt + c*8);
        }
        CP_COMMIT();
    };

    auto compute = [&](int t){
        int buf = t & (STG-1);
        uint32_t as = sb + buf*STGB + wm*32*ROWB;
        uint32_t bs = sb + buf*STGB + ABYTES + wn*NW*ROWB;
#pragma unroll
        for (int s = 0; s < 2; s++){
            uint32_t a[2][4];
#pragma unroll
            for (int im = 0; im < 2; im++){
                uint32_t addr = as + (im*16 + (lane & 7) + ((lane >> 3) & 1)*8)*ROWB
                              + (2*s + (lane >> 4))*16;
                LDSM4(a[im][0], a[im][1], a[im][2], a[im][3], addr);
            }
            uint32_t b[NFR][2];
#pragma unroll
            for (int j = 0; j < NFR/2; j++){
                uint32_t addr = bs + (j*16 + (lane & 7) + (lane >> 4)*8)*ROWB
                              + (2*s + ((lane >> 3) & 1))*16;
                LDSM4(b[2*j][0], b[2*j][1], b[2*j+1][0], b[2*j+1][1], addr);
            }
#pragma unroll
            for (int im = 0; im < 2; im++)
#pragma unroll
                for (int j = 0; j < NFR; j++)
                    MMA16816(acc[im][j], a[im], b[j]);
        }
    };

#pragma unroll
    for (int i = 0; i < STG-1; i++)
        if (i < ntiles) issue(i);

    for (int t = 0; t < ntiles; t++){
        // exact wait: allowed pending = min(STG-2, ntiles-1-t)
        int rem = ntiles - 1 - t;
        if (rem >= 2)      { CP_WAIT(2); }
        else if (rem == 1) { CP_WAIT(1); }
        else               { CP_WAIT(0); }
        __syncthreads();
        if (t + STG-1 < ntiles) issue(t + STG-1);
        compute(t);
    }

    // epilogue
#pragma unroll
    for (int im = 0; im < 2; im++){
        int r = row0 + wm*32 + im*16 + (lane >> 2);
#pragma unroll
        for (int j = 0; j < NFR; j++){
            int c = col0 + wn*NW + j*8 + (lane & 3)*2;
            float v0 = acc[im][j][0], v1 = acc[im][j][1];
            float v2 = acc[im][j][2], v3 = acc[im][j][3];
            if (EPI == 1){
                float b0 = bias[c], b1 = bias[c+1];
                v0 += b0; v1 += b1; v2 += b0; v3 += b1;
                v0 = (v0 > 20.f) ? v0 : log1pf(fexp(v0));
                v1 = (v1 > 20.f) ? v1 : log1pf(fexp(v1));
                v2 = (v2 > 20.f) ? v2 : log1pf(fexp(v2));
                v3 = (v3 > 20.f) ? v3 : log1pf(fexp(v3));
            }
            *reinterpret_cast<float2*>(&Cp[(size_t)r*ldc + c])     = make_float2(v0, v1);
            *reinterpret_cast<float2*>(&Cp[(size_t)(r+8)*ldc + c]) = make_float2(v2, v3);
            if (EPI == 2){
                *reinterpret_cast<__half2*>(&C16[(size_t)r*ldc16 + c])     = __floats2half2_rn(v0, v1);
                *reinterpret_cast<__half2*>(&C16[(size_t)(r+8)*ldc16 + c]) = __floats2half2_rn(v2, v3);
            }
        }
    }
}

// ---------------- split-K reduce for xp gemm ----------------
__global__ void reduce_xp_kernel(){
    int idx = blockIdx.x*blockDim.x + threadIdx.x;
    if (idx >= MROWS*64) return;
    float s = g_part[idx] + g_part[MROWS*64 + idx]
            + g_part[2*MROWS*64 + idx] + g_part[3*MROWS*64 + idx];
    g_xdbl[idx] = s;
    int col = idx & 63;
    if (col < DTRANK){
        int row = idx >> 6;
        g_dtlr16[row*DTRANK + col] = __float2half(s);
    }
}

// ---------------- causal conv1d + silu, plus silu(z) ----------------
__global__ void conv_silu_kernel(const float* __restrict__ cw, const float* __restrict__ cb){
    int idx = blockIdx.x*blockDim.x + threadIdx.x;
    if (idx >= MROWS*DINNER) return;
    int r = idx / DINNER, e = idx % DINNER;
    int b = r / LL, l = r % LL;
    float acc = cb[e];
#pragma unroll
    for (int k = 0; k < DCONV; k++){
        int lp = l - (DCONV-1) + k;
        if (lp >= 0)
            acc += cw[e*DCONV + k] * g_xz[((size_t)(b*LL + lp))*(2*DINNER) + e];
    }
    float u = fsilu(acc);
    g_u[idx] = u;
    g_u16[idx] = __float2half(u);
    float z = g_xz[(size_t)r*(2*DINNER) + DINNER + e];
    g_sz[idx] = fsilu(z);
}

// ---------------- selective scan ----------------
__global__ __launch_bounds__(128)
void scan_kernel(const float* __restrict__ A_log, const float* __restrict__ Dp){
    const int b = blockIdx.y;
    const int w = threadIdx.x >> 5, lane = threadIdx.x & 31;
    const int d  = blockIdx.x*32 + w*8 + (lane & 7);
    const int sq = lane >> 3;

    float a2[4];
#pragma unroll
    for (int k = 0; k < 4; k++)
        a2[k] = -expf(A_log[d*DSTATE + sq*4 + k]) * 1.4426950408889634f;
    const float dp = Dp[d];

    float st[4] = {0.f, 0.f, 0.f, 0.f};
    __shared__ float sBC[64][32];

    for (int t0 = 0; t0 < LL; t0 += 64){
        for (int i = threadIdx.x; i < 64*32; i += 128){
            int tt = i >> 5, j = i & 31;
            sBC[tt][j] = g_xdbl[((size_t)(b*LL + t0 + tt))*64 + DTRANK + j];
        }
        __syncthreads();
#pragma unroll 4
        for (int tt = 0; tt < 64; tt++){
            size_t idx = ((size_t)(b*LL + t0 + tt))*DINNER + d;
            float dt = g_dt[idx];
            float uu = g_u[idx];
            float du = dt*uu;
            float y = 0.f;
#pragma unroll
            for (int k = 0; k < 4; k++){
                float dA = fx2(dt*a2[k]);
                st[k] = dA*st[k] + sBC[tt][sq*4 + k]*du;
                y += st[k]*sBC[tt][16 + sq*4 + k];
            }
            y += __shfl_xor_sync(0xffffffffu, y, 8);
            y += __shfl_xor_sync(0xffffffffu, y, 16);
            if (sq == 0){
                g_y16[idx] = __float2half((y + uu*dp) * g_sz[idx]);
            }
        }
        __syncthreads();
    }
}

// ---------------- final layernorm ----------------
__global__ __launch_bounds__(128)
void ln_kernel(const float* __restrict__ gamma, const float* __restrict__ beta,
               float* __restrict__ out){
    const int m = blockIdx.x;
    const int tid = threadIdx.x;
    const float4 v = reinterpret_cast<const float4*>(g_h + (size_t)m*DMODEL)[tid];
    float s  = v.x + v.y + v.z + v.w;
    float sq = v.x*v.x + v.y*v.y + v.z*v.z + v.w*v.w;
#pragma unroll
    for (int off = 16; off; off >>= 1){
        s  += __shfl_xor_sync(0xffffffffu, s,  off);
        sq += __shfl_xor_sync(0xffffffffu, sq, off);
    }
    __shared__ float r1[4], r2[4];
    if ((tid & 31) == 0){ r1[tid>>5] = s; r2[tid>>5] = sq; }
    __syncthreads();
    s  = r1[0] + r1[1] + r1[2] + r1[3];
    sq = r2[0] + r2[1] + r2[2] + r2[3];
    float mu  = s * (1.f/DMODEL);
    float var = sq * (1.f/DMODEL) - mu*mu;
    float rs  = rsqrtf(var + 1e-5f);
    float4 g4 = reinterpret_cast<const float4*>(gamma)[tid];
    float4 b4 = reinterpret_cast<const float4*>(beta)[tid];
    float4 o;
    o.x = (v.x - mu)*rs*g4.x + b4.x;
    o.y = (v.y - mu)*rs*g4.y + b4.y;
    o.z = (v.z - mu)*rs*g4.z + b4.z;
    o.w = (v.w - mu)*rs*g4.w + b4.w;
    reinterpret_cast<float4*>(out + (size_t)m*DMODEL)[tid] = o;
}

// ---------------- launch ----------------
extern "C" void kernel_launch(void* const* d_in, const int* in_sizes, int n_in,
                              void* d_out, int out_size){
    const float* x       = (const float*)d_in[0];
    const float* in_w    = (const float*)d_in[1];
    const float* in_b    = (const float*)d_in[2];
    const float* W_xz    = (const float*)d_in[3];
    const float* conv_w  = (const float*)d_in[4];
    const float* conv_b  = (const float*)d_in[5];
    const float* W_xp    = (const float*)d_in[6];
    const float* W_dt    = (const float*)d_in[7];
    const float* b_dt    = (const float*)d_in[8];
    const float* A_log   = (const float*)d_in[9];
    const float* D_param = (const float*)d_in[10];
    const float* W_out   = (const float*)d_in[11];
    const float* ln_g    = (const float*)d_in[12];
    const float* ln_b    = (const float*)d_in[13];
    float* out = (float*)d_out;

    float *ph, *pxz, *pdt, *ppart;
    __half *ph16, *pu16, *py16, *pdtlr16, *pw16;
    cudaGetSymbolAddress((void**)&ph,     g_h);
    cudaGetSymbolAddress((void**)&pxz,    g_xz);
    cudaGetSymbolAddress((void**)&pdt,    g_dt);
    cudaGetSymbolAddress((void**)&ppart,  g_part);
    cudaGetSymbolAddress((void**)&ph16,   g_h16);
    cudaGetSymbolAddress((void**)&pu16,   g_u16);
    cudaGetSymbolAddress((void**)&py16,   g_y16);
    cudaGetSymbolAddress((void**)&pdtlr16,g_dtlr16);
    cudaGetSymbolAddress((void**)&pw16,   g_w16);

    const int SM128 = 4*(128*80 + 128*80);   // 81920
    const int SM64  = 4*(128*80 + 64*80);    // 61440
    cudaFuncSetAttribute(gemm_h<128,0>, cudaFuncAttributeMaxDynamicSharedMemorySize, SM128);
    cudaFuncSetAttribute(gemm_h<128,1>, cudaFuncAttributeMaxDynamicSharedMemorySize, SM128);
    cudaFuncSetAttribute(gemm_h<128,2>, cudaFuncAttributeMaxDynamicSharedMemorySize, SM128);
    cudaFuncSetAttribute(gemm_h<64,0>,  cudaFuncAttributeMaxDynamicSharedMemorySize, SM64);

    // Launch order arranged so the harness's single ncu capture (4th launch)
    // lands on the BIG xz GEMM of layer 0.
    f2h_kernel<<<(NDEPTH*SZ_XZ_L/4 + 255)/256, 256>>>(W_xz,  pw16 + OFF_XZ,  NDEPTH*SZ_XZ_L/4);   // 1
    f2h_kernel<<<(NDEPTH*SZ_XP_L/4 + 255)/256, 256>>>(W_xp,  pw16 + OFF_XP,  NDEPTH*SZ_XP_L/4);   // 2
    inproj_kernel<<<(MROWS*DMODEL)/128, 128>>>(x, in_w, in_b);                                     // 3

    // 4 — PROFILED: xz GEMM layer 0   M=4096 N=2048 K=512
    gemm_h<128,0><<<dim3(2048/128, MROWS/128, 1), 256, SM128>>>(
        ph16, pw16 + OFF_XZ, pxz,
        DMODEL, DMODEL, DMODEL, 2*DINNER, nullptr, nullptr, 0, 0);

    f2h_kernel<<<(NDEPTH*SZ_DT_L/4 + 255)/256, 256>>>(W_dt,  pw16 + OFF_DT,  NDEPTH*SZ_DT_L/4);   // 5
    f2h_kernel<<<(NDEPTH*SZ_OUT_L/4 + 255)/256, 256>>>(W_out, pw16 + OFF_OUT, NDEPTH*SZ_OUT_L/4); // 6

    for (int lyr = 0; lyr < NDEPTH; lyr++){
        if (lyr > 0){
            // xz = h @ Wxz^T      M=4096 N=2048 K=512
            gemm_h<128,0><<<dim3(2048/128, MROWS/128, 1), 256, SM128>>>(
                ph16, pw16 + OFF_XZ + (size_t)lyr*SZ_XZ_L, pxz,
                DMODEL, DMODEL, DMODEL, 2*DINNER, nullptr, nullptr, 0, 0);
        }

        conv_silu_kernel<<<(MROWS*DINNER)/256, 256>>>(
            conv_w + (size_t)lyr*DINNER*DCONV, conv_b + (size_t)lyr*DINNER);

        // xdbl = u @ Wxp^T    M=4096 N=64 K=1024, split-K=4
        gemm_h<64,0><<<dim3(1, MROWS/128, 4), 256, SM64>>>(
            pu16, pw16 + OFF_XP + (size_t)lyr*SZ_XP_L, ppart,
            DINNER, DINNER, DINNER, 64, nullptr, nullptr, 0, MROWS*64);

        reduce_xp_kernel<<<(MROWS*64)/256, 256>>>();

        // dt = softplus(dt_lr @ Wdt^T + b_dt)   M=4096 N=1024 K=32
        gemm_h<128,1><<<dim3(DINNER/128, MROWS/128, 1), 256, SM128>>>(
            pdtlr16, pw16 + OFF_DT + (size_t)lyr*SZ_DT_L, pdt,
            DTRANK, DTRANK, DTRANK, DINNER, b_dt + (size_t)lyr*DINNER, nullptr, 0, 0);

        scan_kernel<<<dim3(DINNER/32, BB), 128>>>(
            A_log + (size_t)lyr*DINNER*DSTATE, D_param + (size_t)lyr*DINNER);

        // h = y @ Wout^T      M=4096 N=512 K=1024  (dual write fp32 + fp16)
        gemm_h<128,2><<<dim3(DMODEL/128, MROWS/128, 1), 256, SM128>>>(
            py16, pw16 + OFF_OUT + (size_t)lyr*SZ_OUT_L, ph,
            DINNER, DINNER, DINNER, DMODEL, nullptr, ph16, DMODEL, 0);
    }

    ln_kernel<<<MROWS, 128>>>(ln_g, ln_b, out);
}

// round 7
// speedup vs baseline: 6.5544x; 4.3734x over previous
#include <cuda_runtime.h>
#include <cuda_fp16.h>
#include <cstdio>
#include <cstdint>

#define BB 4
#define LL 1024
#define DIN 8
#define DMODEL 512
#define NDEPTH 4
#define DINNER 1024
#define DSTATE 16
#define DCONV 4
#define DTRANK 32
#define MROWS (BB*LL)   /* 4096 */

// ---------------- scratch ----------------
__device__ float  g_h[MROWS*DMODEL];
__device__ float  g_xz[MROWS*2*DINNER];
__device__ float  g_u[MROWS*DINNER];
__device__ float  g_sz[MROWS*DINNER];
__device__ float  g_xdbl[MROWS*64];
__device__ float  g_dt[MROWS*DINNER];
__device__ float  g_part[4*MROWS*64];

__device__ __half g_h16[MROWS*DMODEL];
__device__ __half g_u16[MROWS*DINNER];
__device__ __half g_y16[MROWS*DINNER];
__device__ __half g_dtlr16[MROWS*DTRANK];
__device__ __half g_w16[6684672];

#define OFF_XZ  0
#define SZ_XZ_L (2048*512)
#define OFF_XP  4194304
#define SZ_XP_L (64*1024)
#define OFF_DT  4456448
#define SZ_DT_L (1024*32)
#define OFF_OUT 4587520
#define SZ_OUT_L (512*1024)

// ---------------- helpers ----------------
__device__ __forceinline__ float fx2(float x){ float y; asm("ex2.approx.f32 %0,%1;" : "=f"(y) : "f"(x)); return y; }
__device__ __forceinline__ float fexp(float x){ return fx2(x*1.4426950408889634f); }
__device__ __forceinline__ float fsilu(float x){ return x/(1.f+fexp(-x)); }
__device__ __forceinline__ uint32_t smem_u32(const void* p){
    uint32_t a; asm("{ .reg .u64 t; cvta.to.shared.u64 t, %1; cvt.u32.u64 %0, t; }" : "=r"(a) : "l"(p));
    return a;
}

#define LDSM4(r0,r1,r2,r3,addr) \
    asm volatile("ldmatrix.sync.aligned.m8n8.x4.shared.b16 {%0,%1,%2,%3}, [%4];" \
        : "=r"(r0),"=r"(r1),"=r"(r2),"=r"(r3) : "r"(addr))

#define MMA16816(d, a, b) \
    asm volatile("mma.sync.aligned.m16n8k16.row.col.f32.f16.f16.f32 " \
        "{%0,%1,%2,%3}, {%4,%5,%6,%7}, {%8,%9}, {%0,%1,%2,%3};" \
        : "+f"((d)[0]), "+f"((d)[1]), "+f"((d)[2]), "+f"((d)[3]) \
        : "r"((a)[0]), "r"((a)[1]), "r"((a)[2]), "r"((a)[3]), \
          "r"((b)[0]), "r"((b)[1]))

#define CP_ASYNC16(saddr, gptr) \
    asm volatile("cp.async.cg.shared.global [%0], [%1], 16;" :: "r"(saddr), "l"(gptr))
#define CP_COMMIT() asm volatile("cp.async.commit_group;")
#define CP_WAIT(n)  asm volatile("cp.async.wait_group %0;" :: "n"(n))

// ---------------- fp32 -> fp16 conversion ----------------
__global__ void f2h_kernel(const float* __restrict__ s, __half* __restrict__ d, int n4){
    int i = blockIdx.x*blockDim.x + threadIdx.x;
    if (i >= n4) return;
    float4 v = reinterpret_cast<const float4*>(s)[i];
    __half2* o = reinterpret_cast<__half2*>(d);
    o[2*i]   = __floats2half2_rn(v.x, v.y);
    o[2*i+1] = __floats2half2_rn(v.z, v.w);
}

// ---------------- input projection ----------------
__global__ void inproj_kernel(const float* __restrict__ x, const float* __restrict__ w,
                              const float* __restrict__ b){
    int idx = blockIdx.x*blockDim.x + threadIdx.x;
    if (idx >= MROWS*DMODEL) return;
    int m = idx / DMODEL, d = idx % DMODEL;
    const float* xr = x + m*DIN;
    const float* wr = w + d*DIN;
    float acc = b[d];
#pragma unroll
    for (int i = 0; i < DIN; i++) acc += xr[i]*wr[i];
    g_h[idx] = acc;
    g_h16[idx] = __float2half(acc);
}

// ---------------- fp16 tensor-core NT GEMM (as round 6) ----------------
template<int BN, int EPI>
__global__ __launch_bounds__(256, 2)
void gemm_h(const __half* __restrict__ A, const __half* __restrict__ B, float* __restrict__ C,
            int K, int lda, int ldb, int ldc, const float* __restrict__ bias,
            __half* __restrict__ C16, int ldc16, int partStride)
{
    constexpr int BM = 128, BK = 32, STG = 4;
    constexpr int NW  = BN/2;
    constexpr int NFR = NW/8;
    constexpr int ROWB = 80;
    constexpr int ABYTES = BM*ROWB;
    constexpr int BBYTES = BN*ROWB;
    constexpr int STGB = ABYTES + BBYTES;

    extern __shared__ char smem[];
    const uint32_t sb = smem_u32(smem);
    const int tid = threadIdx.x, wid = tid >> 5, lane = tid & 31;
    const int wm = wid & 3, wn = wid >> 2;
    const int row0 = blockIdx.y*BM, col0 = blockIdx.x*BN;
    const int kslice = K / gridDim.z;
    const int k0 = blockIdx.z * kslice;
    const int ntiles = kslice / BK;

    const __half* Ag = A + (size_t)row0*lda + k0;
    const __half* Bg = B + (size_t)col0*ldb + k0;
    float* Cp = C + (size_t)blockIdx.z * partStride;

    float acc[2][NFR][4];
#pragma unroll
    for (int i = 0; i < 2; i++)
#pragma unroll
        for (int j = 0; j < NFR; j++)
#pragma unroll
            for (int q = 0; q < 4; q++) acc[i][j][q] = 0.f;

    auto issue = [&](int t){
        int buf = t & (STG-1);
        uint32_t as = sb + buf*STGB;
        uint32_t bs = as + ABYTES;
        int kt = t*BK;
#pragma unroll
        for (int it = 0; it < 2; it++){
            int i = it*256 + tid;
            int r = i >> 2, c = i & 3;
            CP_ASYNC16(as + r*ROWB + c*16, Ag + (size_t)r*lda + kt + c*8);
        }
#pragma unroll
        for (int it = 0; it < BN/64; it++){
            int i = it*256 + tid;
            int r = i >> 2, c = i & 3;
            CP_ASYNC16(bs + r*ROWB + c*16, Bg + (size_t)r*ldb + kt + c*8);
        }
        CP_COMMIT();
    };

    auto compute = [&](int t){
        int buf = t & (STG-1);
        uint32_t as = sb + buf*STGB + wm*32*ROWB;
        uint32_t bs = sb + buf*STGB + ABYTES + wn*NW*ROWB;
#pragma unroll
        for (int s = 0; s < 2; s++){
            uint32_t a[2][4];
#pragma unroll
            for (int im = 0; im < 2; im++){
                uint32_t addr = as + (im*16 + (lane & 7) + ((lane >> 3) & 1)*8)*ROWB
                              + (2*s + (lane >> 4))*16;
                LDSM4(a[im][0], a[im][1], a[im][2], a[im][3], addr);
            }
            uint32_t b[NFR][2];
#pragma unroll
            for (int j = 0; j < NFR/2; j++){
                uint32_t addr = bs + (j*16 + (lane & 7) + (lane >> 4)*8)*ROWB
                              + (2*s + ((lane >> 3) & 1))*16;
                LDSM4(b[2*j][0], b[2*j][1], b[2*j+1][0], b[2*j+1][1], addr);
            }
#pragma unroll
            for (int im = 0; im < 2; im++)
#pragma unroll
                for (int j = 0; j < NFR; j++)
                    MMA16816(acc[im][j], a[im], b[j]);
        }
    };

#pragma unroll
    for (int i = 0; i < STG-1; i++)
        if (i < ntiles) issue(i);

    for (int t = 0; t < ntiles; t++){
        int rem = ntiles - 1 - t;
        if (rem >= 2)      { CP_WAIT(2); }
        else if (rem == 1) { CP_WAIT(1); }
        else               { CP_WAIT(0); }
        __syncthreads();
        if (t + STG-1 < ntiles) issue(t + STG-1);
        compute(t);
    }

#pragma unroll
    for (int im = 0; im < 2; im++){
        int r = row0 + wm*32 + im*16 + (lane >> 2);
#pragma unroll
        for (int j = 0; j < NFR; j++){
            int c = col0 + wn*NW + j*8 + (lane & 3)*2;
            float v0 = acc[im][j][0], v1 = acc[im][j][1];
            float v2 = acc[im][j][2], v3 = acc[im][j][3];
            if (EPI == 1){
                float b0 = bias[c], b1 = bias[c+1];
                v0 += b0; v1 += b1; v2 += b0; v3 += b1;
                v0 = (v0 > 20.f) ? v0 : log1pf(fexp(v0));
                v1 = (v1 > 20.f) ? v1 : log1pf(fexp(v1));
                v2 = (v2 > 20.f) ? v2 : log1pf(fexp(v2));
                v3 = (v3 > 20.f) ? v3 : log1pf(fexp(v3));
            }
            *reinterpret_cast<float2*>(&Cp[(size_t)r*ldc + c])     = make_float2(v0, v1);
            *reinterpret_cast<float2*>(&Cp[(size_t)(r+8)*ldc + c]) = make_float2(v2, v3);
            if (EPI == 2){
                *reinterpret_cast<__half2*>(&C16[(size_t)r*ldc16 + c])     = __floats2half2_rn(v0, v1);
                *reinterpret_cast<__half2*>(&C16[(size_t)(r+8)*ldc16 + c]) = __floats2half2_rn(v2, v3);
            }
        }
    }
}

// ---------------- split-K reduce for xp gemm ----------------
__global__ void reduce_xp_kernel(){
    int idx = blockIdx.x*blockDim.x + threadIdx.x;
    if (idx >= MROWS*64) return;
    float s = g_part[idx] + g_part[MROWS*64 + idx]
            + g_part[2*MROWS*64 + idx] + g_part[3*MROWS*64 + idx];
    g_xdbl[idx] = s;
    int col = idx & 63;
    if (col < DTRANK){
        int row = idx >> 6;
        g_dtlr16[row*DTRANK + col] = __float2half(s);
    }
}

// ---------------- causal conv1d + silu (vectorized: 1 thread = 4 channels) ----------------
__global__ __launch_bounds__(256)
void conv_silu_kernel(const float* __restrict__ cw, const float* __restrict__ cb){
    int idx = blockIdx.x*blockDim.x + threadIdx.x;
    if (idx >= MROWS*(DINNER/4)) return;
    int r = idx >> 8;              // DINNER/4 = 256
    int e = (idx & 255) << 2;
    int b = r / LL, l = r % LL;

    float4 acc = *reinterpret_cast<const float4*>(cb + e);
    float cwv[4][4];
#pragma unroll
    for (int j = 0; j < 4; j++)
        *reinterpret_cast<float4*>(cwv[j]) =
            *reinterpret_cast<const float4*>(cw + (size_t)(e+j)*DCONV);

#pragma unroll
    for (int k = 0; k < DCONV; k++){
        int lp = l - (DCONV-1) + k;
        if (lp >= 0){
            float4 xc = *reinterpret_cast<const float4*>(
                g_xz + (size_t)(b*LL + lp)*(2*DINNER) + e);
            acc.x += cwv[0][k]*xc.x;
            acc.y += cwv[1][k]*xc.y;
            acc.z += cwv[2][k]*xc.z;
            acc.w += cwv[3][k]*xc.w;
        }
    }
    float4 u;
    u.x = fsilu(acc.x); u.y = fsilu(acc.y); u.z = fsilu(acc.z); u.w = fsilu(acc.w);
    size_t o = (size_t)r*DINNER + e;
    *reinterpret_cast<float4*>(g_u + o) = u;
    __half2 h01 = __floats2half2_rn(u.x, u.y);
    __half2 h23 = __floats2half2_rn(u.z, u.w);
    uint2 pk;
    pk.x = *reinterpret_cast<uint32_t*>(&h01);
    pk.y = *reinterpret_cast<uint32_t*>(&h23);
    *reinterpret_cast<uint2*>(g_u16 + o) = pk;

    float4 z = *reinterpret_cast<const float4*>(
        g_xz + (size_t)r*(2*DINNER) + DINNER + e);
    float4 sz;
    sz.x = fsilu(z.x); sz.y = fsilu(z.y); sz.z = fsilu(z.z); sz.w = fsilu(z.w);
    *reinterpret_cast<float4*>(g_sz + o) = sz;
}

// ---------------- selective scan v2: smem-staged, cp.async double buffered ----------------
// grid (DINNER/32, BB) = 128 blocks, 128 threads. 32-step chunks.
__global__ __launch_bounds__(128)
void scan_kernel(const float* __restrict__ A_log, const float* __restrict__ Dp){
    const int b = blockIdx.y;
    const int d0 = blockIdx.x*32;
    const int tid = threadIdx.x;
    const int w = tid >> 5, lane = tid & 31;
    const int col = w*8 + (lane & 7);
    const int d = d0 + col;
    const int sq = lane >> 3;

    __shared__ __align__(16) float s_dt[2][32][32];
    __shared__ __align__(16) float s_u [2][32][32];
    __shared__ __align__(16) float s_sz[2][32][32];
    __shared__ __align__(16) float s_bc[2][32][32];

    float a2[4];
#pragma unroll
    for (int k = 0; k < 4; k++)
        a2[k] = -expf(A_log[d*DSTATE + sq*4 + k]) * 1.4426950408889634f;
    const float dp = Dp[d];
    float st[4] = {0.f, 0.f, 0.f, 0.f};

    auto stage = [&](int c, int buf){
        int t0 = c*32;
#pragma unroll
        for (int kk = 0; kk < 2; kk++){
            int i = tid + kk*128;
            int tt = i >> 3, p = (i & 7) << 2;
            size_t g = ((size_t)(b*LL + t0 + tt))*DINNER + d0 + p;
            CP_ASYNC16(smem_u32(&s_dt[buf][tt][p]), g_dt + g);
            CP_ASYNC16(smem_u32(&s_u [buf][tt][p]), g_u  + g);
            CP_ASYNC16(smem_u32(&s_sz[buf][tt][p]), g_sz + g);
            size_t gb = ((size_t)(b*LL + t0 + tt))*64 + DTRANK + p;
            CP_ASYNC16(smem_u32(&s_bc[buf][tt][p]), g_xdbl + gb);
        }
        CP_COMMIT();
    };

    constexpr int NCH = LL/32;
    stage(0, 0);
    for (int c = 0; c < NCH; c++){
        const int buf = c & 1;
        if (c + 1 < NCH){ stage(c+1, buf^1); CP_WAIT(1); }
        else            { CP_WAIT(0); }
        __syncthreads();
#pragma unroll 8
        for (int tt = 0; tt < 32; tt++){
            float dt = s_dt[buf][tt][col];
            float uu = s_u [buf][tt][col];
            float du = dt*uu;
            float4 Bv = *reinterpret_cast<float4*>(&s_bc[buf][tt][sq*4]);
            float4 Cv = *reinterpret_cast<float4*>(&s_bc[buf][tt][16 + sq*4]);
            float dA0 = fx2(dt*a2[0]);
            float dA1 = fx2(dt*a2[1]);
            float dA2 = fx2(dt*a2[2]);
            float dA3 = fx2(dt*a2[3]);
            st[0] = dA0*st[0] + Bv.x*du;
            st[1] = dA1*st[1] + Bv.y*du;
            st[2] = dA2*st[2] + Bv.z*du;
            st[3] = dA3*st[3] + Bv.w*du;
            float y = st[0]*Cv.x + st[1]*Cv.y + st[2]*Cv.z + st[3]*Cv.w;
            y += __shfl_xor_sync(0xffffffffu, y, 8);
            y += __shfl_xor_sync(0xffffffffu, y, 16);
            if (sq == 0){
                size_t idx = ((size_t)(b*LL + c*32 + tt))*DINNER + d;
                g_y16[idx] = __float2half((y + uu*dp) * s_sz[buf][tt][col]);
            }
        }
        __syncthreads();
    }
}

// ---------------- final layernorm ----------------
__global__ __launch_bounds__(128)
void ln_kernel(const float* __restrict__ gamma, const float* __restrict__ beta,
               float* __restrict__ out){
    const int m = blockIdx.x;
    const int tid = threadIdx.x;
    const float4 v = reinterpret_cast<const float4*>(g_h + (size_t)m*DMODEL)[tid];
    float s  = v.x + v.y + v.z + v.w;
    float sq = v.x*v.x + v.y*v.y + v.z*v.z + v.w*v.w;
#pragma unroll
    for (int off = 16; off; off >>= 1){
        s  += __shfl_xor_sync(0xffffffffu, s,  off);
        sq += __shfl_xor_sync(0xffffffffu, sq, off);
    }
    __shared__ float r1[4], r2[4];
    if ((tid & 31) == 0){ r1[tid>>5] = s; r2[tid>>5] = sq; }
    __syncthreads();
    s  = r1[0] + r1[1] + r1[2] + r1[3];
    sq = r2[0] + r2[1] + r2[2] + r2[3];
    float mu  = s * (1.f/DMODEL);
    float var = sq * (1.f/DMODEL) - mu*mu;
    float rs  = rsqrtf(var + 1e-5f);
    float4 g4 = reinterpret_cast<const float4*>(gamma)[tid];
    float4 b4 = reinterpret_cast<const float4*>(beta)[tid];
    float4 o;
    o.x = (v.x - mu)*rs*g4.x + b4.x;
    o.y = (v.y - mu)*rs*g4.y + b4.y;
    o.z = (v.z - mu)*rs*g4.z + b4.z;
    o.w = (v.w - mu)*rs*g4.w + b4.w;
    reinterpret_cast<float4*>(out + (size_t)m*DMODEL)[tid] = o;
}

// ---------------- launch ----------------
extern "C" void kernel_launch(void* const* d_in, const int* in_sizes, int n_in,
                              void* d_out, int out_size){
    const float* x       = (const float*)d_in[0];
    const float* in_w    = (const float*)d_in[1];
    const float* in_b    = (const float*)d_in[2];
    const float* W_xz    = (const float*)d_in[3];
    const float* conv_w  = (const float*)d_in[4];
    const float* conv_b  = (const float*)d_in[5];
    const float* W_xp    = (const float*)d_in[6];
    const float* W_dt    = (const float*)d_in[7];
    const float* b_dt    = (const float*)d_in[8];
    const float* A_log   = (const float*)d_in[9];
    const float* D_param = (const float*)d_in[10];
    const float* W_out   = (const float*)d_in[11];
    const float* ln_g    = (const float*)d_in[12];
    const float* ln_b    = (const float*)d_in[13];
    float* out = (float*)d_out;

    float *ph, *pxz, *pdt, *ppart;
    __half *ph16, *pu16, *py16, *pdtlr16, *pw16;
    cudaGetSymbolAddress((void**)&ph,     g_h);
    cudaGetSymbolAddress((void**)&pxz,    g_xz);
    cudaGetSymbolAddress((void**)&pdt,    g_dt);
    cudaGetSymbolAddress((void**)&ppart,  g_part);
    cudaGetSymbolAddress((void**)&ph16,   g_h16);
    cudaGetSymbolAddress((void**)&pu16,   g_u16);
    cudaGetSymbolAddress((void**)&py16,   g_y16);
    cudaGetSymbolAddress((void**)&pdtlr16,g_dtlr16);
    cudaGetSymbolAddress((void**)&pw16,   g_w16);

    const int SM128 = 4*(128*80 + 128*80);   // 81920
    const int SM64  = 4*(128*80 + 64*80);    // 61440
    cudaFuncSetAttribute(gemm_h<128,0>, cudaFuncAttributeMaxDynamicSharedMemorySize, SM128);
    cudaFuncSetAttribute(gemm_h<128,1>, cudaFuncAttributeMaxDynamicSharedMemorySize, SM128);
    cudaFuncSetAttribute(gemm_h<128,2>, cudaFuncAttributeMaxDynamicSharedMemorySize, SM128);
    cudaFuncSetAttribute(gemm_h<64,0>,  cudaFuncAttributeMaxDynamicSharedMemorySize, SM64);

    // Launch order: slot 4 (ncu capture) = layer-0 conv_silu (first-ever non-GEMM profile)
    inproj_kernel<<<(MROWS*DMODEL)/128, 128>>>(x, in_w, in_b);                                   // 1
    f2h_kernel<<<(NDEPTH*SZ_XZ_L/4 + 255)/256, 256>>>(W_xz,  pw16 + OFF_XZ,  NDEPTH*SZ_XZ_L/4); // 2

    // 3 — xz GEMM layer 0
    gemm_h<128,0><<<dim3(2048/128, MROWS/128, 1), 256, SM128>>>(
        ph16, pw16 + OFF_XZ, pxz,
        DMODEL, DMODEL, DMODEL, 2*DINNER, nullptr, nullptr, 0, 0);

    // 4 — PROFILED: conv layer 0
    conv_silu_kernel<<<(MROWS*(DINNER/4))/256, 256>>>(conv_w, conv_b);

    f2h_kernel<<<(NDEPTH*SZ_XP_L/4 + 255)/256, 256>>>(W_xp,  pw16 + OFF_XP,  NDEPTH*SZ_XP_L/4); // 5
    f2h_kernel<<<(NDEPTH*SZ_DT_L/4 + 255)/256, 256>>>(W_dt,  pw16 + OFF_DT,  NDEPTH*SZ_DT_L/4); // 6
    f2h_kernel<<<(NDEPTH*SZ_OUT_L/4 + 255)/256, 256>>>(W_out, pw16 + OFF_OUT, NDEPTH*SZ_OUT_L/4);//7

    for (int lyr = 0; lyr < NDEPTH; lyr++){
        if (lyr > 0){
            gemm_h<128,0><<<dim3(2048/128, MROWS/128, 1), 256, SM128>>>(
                ph16, pw16 + OFF_XZ + (size_t)lyr*SZ_XZ_L, pxz,
                DMODEL, DMODEL, DMODEL, 2*DINNER, nullptr, nullptr, 0, 0);
            conv_silu_kernel<<<(MROWS*(DINNER/4))/256, 256>>>(
                conv_w + (size_t)lyr*DINNER*DCONV, conv_b + (size_t)lyr*DINNER);
        }

        // xdbl = u @ Wxp^T    M=4096 N=64 K=1024, split-K=4
        gemm_h<64,0><<<dim3(1, MROWS/128, 4), 256, SM64>>>(
            pu16, pw16 + OFF_XP + (size_t)lyr*SZ_XP_L, ppart,
            DINNER, DINNER, DINNER, 64, nullptr, nullptr, 0, MROWS*64);

        reduce_xp_kernel<<<(MROWS*64)/256, 256>>>();

        // dt = softplus(dt_lr @ Wdt^T + b_dt)   M=4096 N=1024 K=32
        gemm_h<128,1><<<dim3(DINNER/128, MROWS/128, 1), 256, SM128>>>(
            pdtlr16, pw16 + OFF_DT + (size_t)lyr*SZ_DT_L, pdt,
            DTRANK, DTRANK, DTRANK, DINNER, b_dt + (size_t)lyr*DINNER, nullptr, 0, 0);

        scan_kernel<<<dim3(DINNER/32, BB), 128>>>(
            A_log + (size_t)lyr*DINNER*DSTATE, D_param + (size_t)lyr*DINNER);

        // h = y @ Wout^T      M=4096 N=512 K=1024  (dual write fp32 + fp16)
        gemm_h<128,2><<<dim3(DMODEL/128, MROWS/128, 1), 256, SM128>>>(
            py16, pw16 + OFF_OUT + (size_t)lyr*SZ_OUT_L, ph,
            DINNER, DINNER, DINNER, DMODEL, nullptr, ph16, DMODEL, 0);
    }

    ln_kernel<<<MROWS, 128>>>(ln_g, ln_b, out);
}